// round 2
// baseline (speedup 1.0000x reference)
#include <cuda_runtime.h>
#include <cuda_bf16.h>
#include <float.h>

// Problem constants
#define KCODES   4096
#define DIMS     256
#define NROWS    32768            // 32 * 32 * 32
#define ZELEMS   8388608          // 32*256*32*32
#define LOSS_OFF 8388608
#define IDX_OFF  8388609

// Main GEMM tiling
#define ROWS_PER_CTA 64
#define NCTA        (NROWS / ROWS_PER_CTA)   // 512
#define THREADS     256
#define CODES_PER_CHUNK 128                  // 16 tx * 8
#define NCHUNKS     (KCODES / CODES_PER_CHUNK) // 32
#define DCHUNK      32                       // depth chunk
#define NDCHUNKS    (DIMS / DCHUNK)          // 8

#define ZS_STRIDE 68      // 64 rows + pad, float4-aligned
#define CB_STRIDE 132     // 128 codes + pad, float4-aligned

// smem partition (floats)
#define ZS_FLOATS   (DIMS * ZS_STRIDE)        // 17408
#define CBS_FLOATS  (DCHUNK * CB_STRIDE)      // 4224
#define ESQ_FLOATS  (KCODES)                  // 4096
#define ZSQ_FLOATS  (ROWS_PER_CTA)            // 64
#define SMEM_FLOATS (ZS_FLOATS + CBS_FLOATS + ESQ_FLOATS + ZSQ_FLOATS)
#define SMEM_BYTES  (SMEM_FLOATS * 4)         // 103168

__device__ float  g_esq[KCODES];
__device__ int    g_idx[NROWS];
__device__ double g_partials[NCTA];

// ---------------------------------------------------------------------------
// Kernel 1: e_sq[k] = sum_d codebook[k][d]^2   (one warp per code)
// ---------------------------------------------------------------------------
__global__ void vq_esq_kernel(const float* __restrict__ cb) {
    int warp = (blockIdx.x * blockDim.x + threadIdx.x) >> 5;
    int lane = threadIdx.x & 31;
    if (warp >= KCODES) return;
    const float4* row = reinterpret_cast<const float4*>(cb) + (size_t)warp * 64;
    float4 v0 = row[lane];
    float4 v1 = row[lane + 32];
    float s = 0.0f;
    s = fmaf(v0.x, v0.x, s); s = fmaf(v0.y, v0.y, s);
    s = fmaf(v0.z, v0.z, s); s = fmaf(v0.w, v0.w, s);
    s = fmaf(v1.x, v1.x, s); s = fmaf(v1.y, v1.y, s);
    s = fmaf(v1.z, v1.z, s); s = fmaf(v1.w, v1.w, s);
    #pragma unroll
    for (int o = 16; o > 0; o >>= 1) s += __shfl_down_sync(0xffffffffu, s, o);
    if (lane == 0) g_esq[warp] = s;
}

// ---------------------------------------------------------------------------
// Kernel 2: distance GEMM + argmin.
// CTA handles 64 rows; thread (ty,tx) = (tid/16, tid%16) computes a 4x8 tile
// (rows 4*ty..+3, codes tx*8..+7 within each 128-code chunk).
// z tile kept resident in smem (d-major), codebook chunks staged d-major.
// ---------------------------------------------------------------------------
__global__ void __launch_bounds__(THREADS, 2)
vq_main_kernel(const float* __restrict__ z, const float* __restrict__ cb) {
    extern __shared__ float smem[];
    float* zs    = smem;                       // [256][68] d-major z tile
    float* cbs   = zs + ZS_FLOATS;             // [32][132] d-major cb chunk
    float* esq_s = cbs + CBS_FLOATS;           // [4096]
    float* zsq   = esq_s + ESQ_FLOATS;         // [64]

    const int t   = threadIdx.x;
    const int n0  = blockIdx.x * ROWS_PER_CTA;
    const int b   = n0 >> 10;
    const int hw0 = n0 & 1023;
    const float* zb = z + ((size_t)b * 256) * 1024 + hw0;

    // ---- load z tile (d-major) ----
    {
        const int r  = t & 63;
        const int dq = t >> 6;            // 0..3
        #pragma unroll 4
        for (int p = 0; p < 64; ++p) {
            int d = p * 4 + dq;
            zs[d * ZS_STRIDE + r] = zb[(size_t)d * 1024 + r];
        }
    }
    // ---- load e_sq into smem ----
    for (int i = t; i < KCODES; i += THREADS) esq_s[i] = g_esq[i];
    __syncthreads();

    // ---- z_sq per row (warp per 8 rows; any accumulation order is fine) ----
    {
        const int warp = t >> 5;
        const int lane = t & 31;
        for (int rr = warp * 8; rr < warp * 8 + 8; ++rr) {
            float s = 0.0f;
            #pragma unroll
            for (int j = 0; j < 8; ++j) {
                float v = zs[(lane + 32 * j) * ZS_STRIDE + rr];
                s = fmaf(v, v, s);
            }
            #pragma unroll
            for (int o = 16; o > 0; o >>= 1) s += __shfl_down_sync(0xffffffffu, s, o);
            if (lane == 0) zsq[rr] = s;
        }
    }
    __syncthreads();

    const int ty = t >> 4;
    const int tx = t & 15;
    const int r0 = ty * 4;

    float sqv[4];
    #pragma unroll
    for (int i = 0; i < 4; ++i) sqv[i] = zsq[r0 + i];

    float bv[4]; int bi[4];
    #pragma unroll
    for (int i = 0; i < 4; ++i) { bv[i] = FLT_MAX; bi[i] = 0; }

    const float4* cb4 = reinterpret_cast<const float4*>(cb);

    for (int kc = 0; kc < NCHUNKS; ++kc) {
        const int k0 = kc * CODES_PER_CHUNK;

        float acc[4][8];
        #pragma unroll
        for (int i = 0; i < 4; ++i)
            #pragma unroll
            for (int j = 0; j < 8; ++j) acc[i][j] = 0.0f;

        // prefetch depth-chunk 0 into registers
        float4 pf[4];
        #pragma unroll
        for (int it = 0; it < 4; ++it) {
            int idx = it * 256 + t;
            int c = idx >> 3, q = idx & 7;
            pf[it] = cb4[(size_t)(k0 + c) * 64 + q];
        }

        for (int dc = 0; dc < NDCHUNKS; ++dc) {
            __syncthreads();   // previous chunk's compute done
            // stage registers -> smem (transpose to d-major)
            #pragma unroll
            for (int it = 0; it < 4; ++it) {
                int idx = it * 256 + t;
                int c = idx >> 3, q = idx & 7;
                float* p = &cbs[(q * 4) * CB_STRIDE + c];
                p[0 * CB_STRIDE] = pf[it].x;
                p[1 * CB_STRIDE] = pf[it].y;
                p[2 * CB_STRIDE] = pf[it].z;
                p[3 * CB_STRIDE] = pf[it].w;
            }
            __syncthreads();
            // prefetch next depth chunk
            if (dc + 1 < NDCHUNKS) {
                #pragma unroll
                for (int it = 0; it < 4; ++it) {
                    int idx = it * 256 + t;
                    int c = idx >> 3, q = idx & 7;
                    pf[it] = cb4[(size_t)(k0 + c) * 64 + (dc + 1) * 8 + q];
                }
            }
            const int dbase = dc * DCHUNK;
            #pragma unroll 8
            for (int dd = 0; dd < DCHUNK; ++dd) {
                const float4 a4 = *reinterpret_cast<const float4*>(
                    &zs[(dbase + dd) * ZS_STRIDE + r0]);
                const float4 b0 = *reinterpret_cast<const float4*>(
                    &cbs[dd * CB_STRIDE + tx * 8]);
                const float4 b1 = *reinterpret_cast<const float4*>(
                    &cbs[dd * CB_STRIDE + tx * 8 + 4]);
                const float a[4]  = {a4.x, a4.y, a4.z, a4.w};
                const float bb[8] = {b0.x, b0.y, b0.z, b0.w,
                                     b1.x, b1.y, b1.z, b1.w};
                #pragma unroll
                for (int i = 0; i < 4; ++i)
                    #pragma unroll
                    for (int j = 0; j < 8; ++j)
                        acc[i][j] = fmaf(a[i], bb[j], acc[i][j]);
            }
        }

        // distances + running argmin.
        // Replicate reference rounding exactly: fl(fl(z_sq - 2*dot) + e_sq).
        // (2*dot is exact; each combine uses one correctly-rounded fp32 op.)
        #pragma unroll
        for (int j = 0; j < 8; ++j) {
            int k = k0 + tx * 8 + j;
            float e = esq_s[k];
            #pragma unroll
            for (int i = 0; i < 4; ++i) {
                float dist = __fadd_rn(__fsub_rn(sqv[i],
                                 __fmul_rn(2.0f, acc[i][j])), e);
                if (dist < bv[i]) { bv[i] = dist; bi[i] = k; }  // strict <: first idx wins
            }
        }
    }

    // reduce across the 16 tx threads (one half-warp per row group)
    #pragma unroll
    for (int i = 0; i < 4; ++i) {
        float v = bv[i]; int x = bi[i];
        #pragma unroll
        for (int off = 8; off > 0; off >>= 1) {
            float ov = __shfl_down_sync(0xffffffffu, v, off, 16);
            int   ox = __shfl_down_sync(0xffffffffu, x, off, 16);
            if (ov < v || (ov == v && ox < x)) { v = ov; x = ox; }
        }
        if (tx == 0) g_idx[n0 + r0 + i] = x;
    }
}

// ---------------------------------------------------------------------------
// Kernel 3: gather codebook rows, write z_q_st (+ indices-as-float), and
// per-block double loss partials.
// ---------------------------------------------------------------------------
__global__ void __launch_bounds__(THREADS)
vq_epilogue_kernel(const float* __restrict__ z, const float* __restrict__ cb,
                   float* __restrict__ out, int out_size) {
    __shared__ int idx_s[ROWS_PER_CTA];
    __shared__ double red[THREADS];

    const int t  = threadIdx.x;
    const int n0 = blockIdx.x * ROWS_PER_CTA;

    if (t < ROWS_PER_CTA) {
        int ii = g_idx[n0 + t];
        idx_s[t] = ii;
        int oi = IDX_OFF + n0 + t;
        if (oi < out_size) out[oi] = (float)ii;  // indices cast to f32 (exact)
    }
    __syncthreads();

    const int b   = n0 >> 10;
    const int hw0 = n0 & 1023;
    const float* zb = z + ((size_t)b * 256) * 1024 + hw0;
    float*       ob = out + ((size_t)b * 256) * 1024 + hw0;

    const int r  = t & 63;
    const int dq = t >> 6;                 // thread owns d in [dq*64, dq*64+64)
    const float* cbrow = cb + (size_t)idx_s[r] * DIMS;

    double accd = 0.0;
    #pragma unroll 4
    for (int p4 = 0; p4 < 16; ++p4) {
        const float4 q4 = *reinterpret_cast<const float4*>(cbrow + dq * 64 + p4 * 4);
        const float qv[4] = {q4.x, q4.y, q4.z, q4.w};
        #pragma unroll
        for (int j = 0; j < 4; ++j) {
            int d = dq * 64 + p4 * 4 + j;
            float zv = zb[(size_t)d * 1024 + r];
            float diff = __fsub_rn(qv[j], zv);
            ob[(size_t)d * 1024 + r] = __fadd_rn(zv, diff);  // straight-through
            accd = fma((double)diff, (double)diff, accd);
        }
    }

    red[t] = accd;
    __syncthreads();
    for (int s = THREADS / 2; s > 0; s >>= 1) {
        if (t < s) red[t] += red[t + s];
        __syncthreads();
    }
    if (t == 0) g_partials[blockIdx.x] = red[0];
}

// ---------------------------------------------------------------------------
// Kernel 4: final loss reduction (deterministic fixed-order tree).
// vq_loss = mean + 0.25*mean  (codebook_loss == commitment_loss numerically)
// ---------------------------------------------------------------------------
__global__ void vq_finalize_kernel(float* __restrict__ out, int out_size) {
    __shared__ double red[256];
    const int t = threadIdx.x;
    red[t] = g_partials[t] + g_partials[t + 256];
    __syncthreads();
    for (int s = 128; s > 0; s >>= 1) {
        if (t < s) red[t] += red[t + s];
        __syncthreads();
    }
    if (t == 0 && LOSS_OFF < out_size) {
        double mean = red[0] / (double)ZELEMS;
        float m = (float)mean;
        out[LOSS_OFF] = __fadd_rn(m, __fmul_rn(0.25f, m));
    }
}

// ---------------------------------------------------------------------------
extern "C" void kernel_launch(void* const* d_in, const int* in_sizes, int n_in,
                              void* d_out, int out_size) {
    const float* z  = (const float*)d_in[0];
    const float* cb = (const float*)d_in[1];
    // defensive: detect swapped input order by element count
    if (n_in >= 2 && in_sizes[0] == KCODES * DIMS && in_sizes[1] == ZELEMS) {
        const float* tmp = z; z = cb; cb = tmp;
    }
    float* out = (float*)d_out;

    cudaFuncSetAttribute(vq_main_kernel,
                         cudaFuncAttributeMaxDynamicSharedMemorySize, SMEM_BYTES);

    vq_esq_kernel<<<KCODES / 8, 256>>>(cb);
    vq_main_kernel<<<NCTA, THREADS, SMEM_BYTES>>>(z, cb);
    vq_epilogue_kernel<<<NCTA, THREADS>>>(z, cb, out, out_size);
    vq_finalize_kernel<<<1, 256>>>(out, out_size);
}